// round 3
// baseline (speedup 1.0000x reference)
#include <cuda_runtime.h>

#define FULL 0xffffffffu
#define L2E 1.4426950408889634f

// shared layout offsets (floats), all lane-fastest (conflict-free)
#define L0W 0      // [t*32+lane] = w0[255-(lane*8+t)]       (256)
#define L0B 256    // [t*32+lane] = b0[510-(lane*8+t)]       (256)
#define L1Wa 512   // [s*32+lane] = w1[2*(lane*4+s)]         (128)
#define L1Wb 640   // [s*32+lane] = w1[2*(lane*4+s)+1]       (128)
#define L1B 768    // [s*32+lane] = b1[127+lane*4+s]         (128)
#define L2Wa 896   // [s*32+lane] = w2[2*(lane*2+s)]         (64)
#define L2Wb 960
#define L2B 1024   // b2[63+lane*2+s]
#define L3Wa 1088  // [lane] = w3[2*lane]                    (32)
#define L3Wb 1120
#define L3B 1152   // b3[31+lane]
#define L4W 1184   // w4[0..31] raw
#define L4B 1216   // b4[15+k], k=0..15
#define L5W 1232   // w5[0..15]
#define L5B 1248   // b5[7+k]
#define L6W 1256   // w6[0..7]
#define L6B 1264   // b6[3+k]
#define L7W 1268   // w7[0..3]
#define L7B 1272   // b7[1+k]
#define L8W 1274   // w8[0..1]
#define L8B 1276   // b8[0]
#define SC  1280   // alpha,beta,gamma,root_w,root_b
#define SM_TOT 1288

struct TreeParams {
    const float* w[9];
    const float* b[9];
    const float* alpha;
    const float* beta;
    const float* gamma;
    const float* root_w;
    const float* root_b;
};

__device__ __forceinline__ float ex2f(float x) {
    float y; asm("ex2.approx.ftz.f32 %0, %1;" : "=f"(y) : "f"(x)); return y;
}
__device__ __forceinline__ float rcpf(float x) {
    float y; asm("rcp.approx.ftz.f32 %0, %1;" : "=f"(y) : "f"(x)); return y;
}

// Single-reciprocal nck over the common denominator (1+e1)(1+e2)(0.436+e3).
// Clamp z at -170: all terms < 1e-9 there; keeps the product finite.
__device__ __forceinline__ float nck_eval(float z, float cA, float dA,
                                          float cB, float dB, float cG) {
    z = fmaxf(z, -170.0f);
    const float e1 = ex2f(fmaf(-L2E / 8.98f, z, 6.39f * L2E));
    const float e2 = ex2f(fmaf(-L2E / 4.25f, z, -4.4f * L2E));
    const float e3 = ex2f(fmaf(-0.132f * L2E, z, 0.132f * 16.74f * L2E));
    const float a1 = 1.0f + e1;
    const float a2 = 1.0f + e2;
    const float a3 = 0.436f + e3;
    const float d12 = a1 * a2;
    const float R = rcpf(d12 * a3);
    const float n1 = fmaf(cA, z, dA);
    const float n2 = fmaf(cB, z, dB);
    const float q = fmaf(n1, a2, n2 * a1);
    const float num = fmaf(q, a3, cG * d12);
    return num * R;
}

__global__ __launch_bounds__(256, 4) void asym_tree_kernel(
    const float* __restrict__ x, TreeParams P, float* __restrict__ out, int B) {
    __shared__ float sm[SM_TOT];

    const int tid = threadIdx.x;
    const int lane = tid & 31;

    // ---- stage params, lane-fastest transposed layouts ----
    {
        const int t = tid >> 5, l = tid & 31;
        const int r = l * 8 + t;
        sm[L0W + tid] = P.w[0][255 - r];
        sm[L0B + tid] = P.b[0][510 - r];
    }
    if (tid < 128) {
        const int s = tid >> 5, l = tid & 31;
        const int k = l * 4 + s;
        sm[L1Wa + tid] = P.w[1][2 * k];
        sm[L1Wb + tid] = P.w[1][2 * k + 1];
        sm[L1B + tid]  = P.b[1][127 + k];
    }
    if (tid < 64) {
        const int s = tid >> 5, l = tid & 31;
        const int k = l * 2 + s;
        sm[L2Wa + tid] = P.w[2][2 * k];
        sm[L2Wb + tid] = P.w[2][2 * k + 1];
        sm[L2B + tid]  = P.b[2][63 + k];
    }
    if (tid < 32) {
        sm[L3Wa + tid] = P.w[3][2 * tid];
        sm[L3Wb + tid] = P.w[3][2 * tid + 1];
        sm[L3B + tid]  = P.b[3][31 + tid];
        sm[L4W + tid]  = P.w[4][tid];
    }
    if (tid < 16) {
        sm[L4B + tid] = P.b[4][15 + tid];
        sm[L5W + tid] = P.w[5][tid];
    }
    if (tid < 8) {
        sm[L5B + tid] = P.b[5][7 + tid];
        sm[L6W + tid] = P.w[6][tid];
    }
    if (tid < 4) {
        sm[L6B + tid] = P.b[6][3 + tid];
        sm[L7W + tid] = P.w[7][tid];
    }
    if (tid < 2) {
        sm[L7B + tid] = P.b[7][1 + tid];
        sm[L8W + tid] = P.w[8][tid];
    }
    if (tid == 0) {
        sm[L8B] = P.b[8][0];
        sm[SC + 0] = P.alpha[0];  sm[SC + 1] = P.beta[0]; sm[SC + 2] = P.gamma[0];
        sm[SC + 3] = P.root_w[0]; sm[SC + 4] = P.root_b[0];
    }
    __syncthreads();

    const float A = sm[SC], Bt = sm[SC + 1], G = sm[SC + 2];
    const float cA = A * 0.0878f, dA = -A * 0.0878f * 113.68f;
    const float cB = Bt * 0.129f, dB = -Bt * 0.129f * 69.62f;
    const float cG = G * 2.23f;

    const int warp = (blockIdx.x * 256 + tid) >> 5;
    const int e0 = warp * 4;
    if (e0 >= B) return;

    // ---- per-element levels 0-3 -> c[ei] = v3 (natural order, one value/lane) ----
    float c[4];
#pragma unroll
    for (int ei = 0; ei < 4; ++ei) {
        const int e = e0 + ei;
        const float* xe = x + (size_t)(e < B ? e : B - 1) * 256;
        const float4 xa = reinterpret_cast<const float4*>(xe)[lane * 2];
        const float4 xb = reinterpret_cast<const float4*>(xe)[lane * 2 + 1];
        const float xv[8] = {xa.x, xa.y, xa.z, xa.w, xb.x, xb.y, xb.z, xb.w};

        float u[8];
#pragma unroll
        for (int t = 0; t < 8; ++t) {
            const float z = fmaf(sm[L0W + t * 32 + lane], xv[t],
                                 sm[L0B + t * 32 + lane]);
            u[t] = nck_eval(z, cA, dA, cB, dB, cG);
        }

        // level 1: N=128, 4 outputs/lane
        float t1[4];
#pragma unroll
        for (int s = 0; s < 4; ++s) {
            const float z = fmaf(sm[L1Wa + s * 32 + lane], u[2 * s],
                           fmaf(sm[L1Wb + s * 32 + lane], u[2 * s + 1],
                                sm[L1B + s * 32 + lane]));
            t1[s] = nck_eval(z, cA, dA, cB, dB, cG);
        }
#pragma unroll
        for (int s = 0; s < 4; ++s) u[s] = __shfl_xor_sync(FULL, t1[3 - s], 31);

        // level 2: N=64, 2 outputs/lane
        float t2[2];
#pragma unroll
        for (int s = 0; s < 2; ++s) {
            const float z = fmaf(sm[L2Wa + s * 32 + lane], u[2 * s],
                           fmaf(sm[L2Wb + s * 32 + lane], u[2 * s + 1],
                                sm[L2B + s * 32 + lane]));
            t2[s] = nck_eval(z, cA, dA, cB, dB, cG);
        }
        u[0] = __shfl_xor_sync(FULL, t2[1], 31);
        u[1] = __shfl_xor_sync(FULL, t2[0], 31);

        // level 3: N=32, 1 output/lane -> NATURAL order
        const float z3 = fmaf(sm[L3Wa + lane], u[0],
                        fmaf(sm[L3Wb + lane], u[1], sm[L3B + lane]));
        c[ei] = nck_eval(z3, cA, dA, cB, dB, cG);
    }

    // ---- level 4: N=16, 2 elements per warp-nck ----
    const bool hi = lane >= 16;
    const int k4 = lane & 15;
    const int i4a = 31 - 2 * k4;
    const int i4b = 30 - 2 * k4;
    const float w4a = sm[L4W + 2 * k4], w4b = sm[L4W + 2 * k4 + 1];
    const float bb4 = sm[L4B + k4];

    float v4p0, v4p1;
    {
        const float a0 = __shfl_sync(FULL, c[0], i4a);
        const float a1 = __shfl_sync(FULL, c[1], i4a);
        const float b0 = __shfl_sync(FULL, c[0], i4b);
        const float b1 = __shfl_sync(FULL, c[1], i4b);
        const float pa = hi ? a1 : a0;
        const float pb = hi ? b1 : b0;
        v4p0 = nck_eval(fmaf(w4a, pa, fmaf(w4b, pb, bb4)), cA, dA, cB, dB, cG);
    }
    {
        const float a0 = __shfl_sync(FULL, c[2], i4a);
        const float a1 = __shfl_sync(FULL, c[3], i4a);
        const float b0 = __shfl_sync(FULL, c[2], i4b);
        const float b1 = __shfl_sync(FULL, c[3], i4b);
        const float pa = hi ? a1 : a0;
        const float pb = hi ? b1 : b0;
        v4p1 = nck_eval(fmaf(w4a, pa, fmaf(w4b, pb, bb4)), cA, dA, cB, dB, cG);
    }

    // ---- level 5: N=8, all 4 elements in one warp-nck ----
    float v5;
    {
        const int k5 = lane & 7;
        const int half = (lane >> 3) & 1;
        const int s5a = half * 16 + (15 - 2 * k5);
        const int s5b = s5a - 1;
        const float w5a = sm[L5W + 2 * k5], w5b = sm[L5W + 2 * k5 + 1];
        const float bb5 = sm[L5B + k5];
        const float A0 = __shfl_sync(FULL, v4p0, s5a);
        const float A1 = __shfl_sync(FULL, v4p1, s5a);
        const float B0 = __shfl_sync(FULL, v4p0, s5b);
        const float B1 = __shfl_sync(FULL, v4p1, s5b);
        const float pa = hi ? A1 : A0;
        const float pb = hi ? B1 : B0;
        v5 = nck_eval(fmaf(w5a, pa, fmaf(w5b, pb, bb5)), cA, dA, cB, dB, cG);
    }
    // v5: lane = 8*e + k

    // ---- level 6: N=4 (lane = 4e + k, lanes 0-15 valid) ----
    float v6;
    {
        const int k6 = lane & 3;
        const int e6 = lane >> 2;
        const int s6 = (8 * e6 + 7 - 2 * k6) & 31;
        const float w6a = sm[L6W + 2 * k6], w6b = sm[L6W + 2 * k6 + 1];
        const float bb6 = sm[L6B + k6];
        const float pa = __shfl_sync(FULL, v5, s6);
        const float pb = __shfl_sync(FULL, v5, (s6 - 1) & 31);
        v6 = nck_eval(fmaf(w6a, pa, fmaf(w6b, pb, bb6)), cA, dA, cB, dB, cG);
    }

    // ---- level 7: N=2 (lane = 2e + k, lanes 0-7 valid) ----
    float v7;
    {
        const int k7 = lane & 1;
        const int e7 = (lane >> 1) & 7;
        const int s7 = (4 * e7 + 3 - 2 * k7) & 31;
        const float w7a = sm[L7W + 2 * k7], w7b = sm[L7W + 2 * k7 + 1];
        const float bb7 = sm[L7B + k7];
        const float pa = __shfl_sync(FULL, v6, s7);
        const float pb = __shfl_sync(FULL, v6, (s7 - 1) & 31);
        v7 = nck_eval(fmaf(w7a, pa, fmaf(w7b, pb, bb7)), cA, dA, cB, dB, cG);
    }

    // ---- level 8: N=1 (lane = e, lanes 0-3 valid) ----
    {
        const int e8 = lane & 3;
        const float pa = __shfl_sync(FULL, v7, (2 * e8 + 1) & 31);
        const float pb = __shfl_sync(FULL, v7, (2 * e8) & 31);
        const float v8 = nck_eval(fmaf(sm[L8W], pa, fmaf(sm[L8W + 1], pb, sm[L8B])),
                                  cA, dA, cB, dB, cG);
        if (lane < 4 && e0 + lane < B) {
            const float t = fmaf(v8, sm[SC + 3], sm[SC + 4]);
            out[e0 + lane] = rcpf(1.0f + ex2f(-t * L2E));
        }
    }
}

extern "C" void kernel_launch(void* const* d_in, const int* in_sizes, int n_in,
                              void* d_out, int out_size) {
    const float* x = (const float*)d_in[0];
    TreeParams P;
    if (in_sizes[2] == 511) {
        for (int l = 0; l < 9; ++l) {
            P.w[l] = (const float*)d_in[1 + 2 * l];
            P.b[l] = (const float*)d_in[2 + 2 * l];
        }
    } else {
        for (int l = 0; l < 9; ++l) {
            P.w[l] = (const float*)d_in[1 + l];
            P.b[l] = (const float*)d_in[10 + l];
        }
    }
    P.alpha  = (const float*)d_in[19];
    P.beta   = (const float*)d_in[20];
    P.gamma  = (const float*)d_in[21];
    P.root_w = (const float*)d_in[22];
    P.root_b = (const float*)d_in[23];

    const int B = in_sizes[0] / 256;              // 32768
    const int warps = (B + 3) / 4;                // 4 elements per warp
    const int grid = (warps + 7) / 8;             // 8 warps per 256-thread block
    asym_tree_kernel<<<grid, 256>>>(x, P, (float*)d_out, B);
}

// round 4
// speedup vs baseline: 1.5015x; 1.5015x over previous
#include <cuda_runtime.h>

#define FULL 0xffffffffu
#define L2E 1.4426950408889634f

// shared layout offsets (floats), all lane-fastest (conflict-free)
#define L0W 0      // [t*32+lane] = w0[255-(lane*8+t)]       (256)
#define L0B 256    // [t*32+lane] = b0[510-(lane*8+t)]       (256)
#define L1Wa 512   // [s*32+lane] = w1[2*(lane*4+s)]         (128)
#define L1Wb 640   // [s*32+lane] = w1[2*(lane*4+s)+1]       (128)
#define L1B 768    // [s*32+lane] = b1[127+lane*4+s]         (128)
#define L2Wa 896   // [s*32+lane] = w2[2*(lane*2+s)]         (64)
#define L2Wb 960
#define L2B 1024   // b2[63+lane*2+s]
#define L3Wa 1088  // [lane] = w3[2*lane]                    (32)
#define L3Wb 1120
#define L3B 1152   // b3[31+lane]
#define L4W 1184   // w4[0..31] raw
#define L4B 1216   // b4[15+k], k=0..15
#define L5W 1232   // w5[0..15]
#define L5B 1248   // b5[7+k]
#define L6W 1256   // w6[0..7]
#define L6B 1264   // b6[3+k]
#define L7W 1268   // w7[0..3]
#define L7B 1272   // b7[1+k]
#define L8W 1274   // w8[0..1]
#define L8B 1276   // b8[0]
#define SC  1280   // alpha,beta,gamma,root_w,root_b
#define SM_TOT 1288

struct TreeParams {
    const float* w[9];
    const float* b[9];
    const float* alpha;
    const float* beta;
    const float* gamma;
    const float* root_w;
    const float* root_b;
};

__device__ __forceinline__ float ex2f(float x) {
    float y; asm("ex2.approx.ftz.f32 %0, %1;" : "=f"(y) : "f"(x)); return y;
}
__device__ __forceinline__ float rcpf(float x) {
    float y; asm("rcp.approx.ftz.f32 %0, %1;" : "=f"(y) : "f"(x)); return y;
}

// Single-reciprocal nck over the common denominator (1+e1)(1+e2)(0.436+e3).
// Clamp z at -170: all terms < 1e-9 there; keeps the product finite.
__device__ __forceinline__ float nck_eval(float z, float cA, float dA,
                                          float cB, float dB, float cG) {
    z = fmaxf(z, -170.0f);
    const float e1 = ex2f(fmaf(-L2E / 8.98f, z, 6.39f * L2E));
    const float e2 = ex2f(fmaf(-L2E / 4.25f, z, -4.4f * L2E));
    const float e3 = ex2f(fmaf(-0.132f * L2E, z, 0.132f * 16.74f * L2E));
    const float a1 = 1.0f + e1;
    const float a2 = 1.0f + e2;
    const float a3 = 0.436f + e3;
    const float d12 = a1 * a2;
    const float R = rcpf(d12 * a3);
    const float n1 = fmaf(cA, z, dA);
    const float n2 = fmaf(cB, z, dB);
    const float q = fmaf(n1, a2, n2 * a1);
    const float num = fmaf(q, a3, cG * d12);
    return num * R;
}

__global__ __launch_bounds__(256) void asym_tree_kernel(
    const float* __restrict__ x, TreeParams P, float* __restrict__ out, int B) {
    __shared__ float sm[SM_TOT];

    const int tid = threadIdx.x;
    const int lane = tid & 31;

    // ---- stage params, lane-fastest transposed layouts ----
    {
        const int t = tid >> 5, l = tid & 31;
        const int r = l * 8 + t;
        sm[L0W + tid] = P.w[0][255 - r];
        sm[L0B + tid] = P.b[0][510 - r];
    }
    if (tid < 128) {
        const int s = tid >> 5, l = tid & 31;
        const int k = l * 4 + s;
        sm[L1Wa + tid] = P.w[1][2 * k];
        sm[L1Wb + tid] = P.w[1][2 * k + 1];
        sm[L1B + tid]  = P.b[1][127 + k];
    }
    if (tid < 64) {
        const int s = tid >> 5, l = tid & 31;
        const int k = l * 2 + s;
        sm[L2Wa + tid] = P.w[2][2 * k];
        sm[L2Wb + tid] = P.w[2][2 * k + 1];
        sm[L2B + tid]  = P.b[2][63 + k];
    }
    if (tid < 32) {
        sm[L3Wa + tid] = P.w[3][2 * tid];
        sm[L3Wb + tid] = P.w[3][2 * tid + 1];
        sm[L3B + tid]  = P.b[3][31 + tid];
        sm[L4W + tid]  = P.w[4][tid];
    }
    if (tid < 16) {
        sm[L4B + tid] = P.b[4][15 + tid];
        sm[L5W + tid] = P.w[5][tid];
    }
    if (tid < 8) {
        sm[L5B + tid] = P.b[5][7 + tid];
        sm[L6W + tid] = P.w[6][tid];
    }
    if (tid < 4) {
        sm[L6B + tid] = P.b[6][3 + tid];
        sm[L7W + tid] = P.w[7][tid];
    }
    if (tid < 2) {
        sm[L7B + tid] = P.b[7][1 + tid];
        sm[L8W + tid] = P.w[8][tid];
    }
    if (tid == 0) {
        sm[L8B] = P.b[8][0];
        sm[SC + 0] = P.alpha[0];  sm[SC + 1] = P.beta[0]; sm[SC + 2] = P.gamma[0];
        sm[SC + 3] = P.root_w[0]; sm[SC + 4] = P.root_b[0];
    }
    __syncthreads();

    const float A = sm[SC], Bt = sm[SC + 1], G = sm[SC + 2];
    const float cA = A * 0.0878f, dA = -A * 0.0878f * 113.68f;
    const float cB = Bt * 0.129f, dB = -Bt * 0.129f * 69.62f;
    const float cG = G * 2.23f;

    const int warp = (blockIdx.x * 256 + tid) >> 5;
    const int e0 = warp * 4;
    if (e0 >= B) return;

    // ---- per-element levels 0-3 -> c[ei] = v3 (natural order, one value/lane) ----
    float c[4];
#pragma unroll
    for (int ei = 0; ei < 4; ++ei) {
        const int e = e0 + ei;
        const float* xe = x + (size_t)(e < B ? e : B - 1) * 256;
        const float4 xa = reinterpret_cast<const float4*>(xe)[lane * 2];
        const float4 xb = reinterpret_cast<const float4*>(xe)[lane * 2 + 1];
        const float xv[8] = {xa.x, xa.y, xa.z, xa.w, xb.x, xb.y, xb.z, xb.w};

        // levels 0+1 fused: per pair compute u0,u1 then immediately t1[s]
        // (keeps only ~2 u values live instead of 8)
        float t1[4];
#pragma unroll
        for (int s = 0; s < 4; ++s) {
            const float u0 = nck_eval(fmaf(sm[L0W + (2 * s) * 32 + lane], xv[2 * s],
                                           sm[L0B + (2 * s) * 32 + lane]),
                                      cA, dA, cB, dB, cG);
            const float u1 = nck_eval(fmaf(sm[L0W + (2 * s + 1) * 32 + lane], xv[2 * s + 1],
                                           sm[L0B + (2 * s + 1) * 32 + lane]),
                                      cA, dA, cB, dB, cG);
            const float z = fmaf(sm[L1Wa + s * 32 + lane], u0,
                           fmaf(sm[L1Wb + s * 32 + lane], u1,
                                sm[L1B + s * 32 + lane]));
            t1[s] = nck_eval(z, cA, dA, cB, dB, cG);
        }

        // reversal for level 2 inputs
        float u[4];
#pragma unroll
        for (int s = 0; s < 4; ++s) u[s] = __shfl_xor_sync(FULL, t1[3 - s], 31);

        // level 2: N=64, 2 outputs/lane
        float t2[2];
#pragma unroll
        for (int s = 0; s < 2; ++s) {
            const float z = fmaf(sm[L2Wa + s * 32 + lane], u[2 * s],
                           fmaf(sm[L2Wb + s * 32 + lane], u[2 * s + 1],
                                sm[L2B + s * 32 + lane]));
            t2[s] = nck_eval(z, cA, dA, cB, dB, cG);
        }
        const float r0 = __shfl_xor_sync(FULL, t2[1], 31);
        const float r1 = __shfl_xor_sync(FULL, t2[0], 31);

        // level 3: N=32, 1 output/lane -> NATURAL order
        const float z3 = fmaf(sm[L3Wa + lane], r0,
                        fmaf(sm[L3Wb + lane], r1, sm[L3B + lane]));
        c[ei] = nck_eval(z3, cA, dA, cB, dB, cG);
    }

    // ---- level 4: N=16, 2 elements per warp-nck ----
    const bool hi = lane >= 16;
    const int k4 = lane & 15;
    const int i4a = 31 - 2 * k4;
    const int i4b = 30 - 2 * k4;
    const float w4a = sm[L4W + 2 * k4], w4b = sm[L4W + 2 * k4 + 1];
    const float bb4 = sm[L4B + k4];

    float v4p0, v4p1;
    {
        const float a0 = __shfl_sync(FULL, c[0], i4a);
        const float a1 = __shfl_sync(FULL, c[1], i4a);
        const float b0 = __shfl_sync(FULL, c[0], i4b);
        const float b1 = __shfl_sync(FULL, c[1], i4b);
        const float pa = hi ? a1 : a0;
        const float pb = hi ? b1 : b0;
        v4p0 = nck_eval(fmaf(w4a, pa, fmaf(w4b, pb, bb4)), cA, dA, cB, dB, cG);
    }
    {
        const float a0 = __shfl_sync(FULL, c[2], i4a);
        const float a1 = __shfl_sync(FULL, c[3], i4a);
        const float b0 = __shfl_sync(FULL, c[2], i4b);
        const float b1 = __shfl_sync(FULL, c[3], i4b);
        const float pa = hi ? a1 : a0;
        const float pb = hi ? b1 : b0;
        v4p1 = nck_eval(fmaf(w4a, pa, fmaf(w4b, pb, bb4)), cA, dA, cB, dB, cG);
    }

    // ---- level 5: N=8, all 4 elements in one warp-nck ----
    float v5;
    {
        const int k5 = lane & 7;
        const int half = (lane >> 3) & 1;
        const int s5a = half * 16 + (15 - 2 * k5);
        const int s5b = s5a - 1;
        const float w5a = sm[L5W + 2 * k5], w5b = sm[L5W + 2 * k5 + 1];
        const float bb5 = sm[L5B + k5];
        const float A0 = __shfl_sync(FULL, v4p0, s5a);
        const float A1 = __shfl_sync(FULL, v4p1, s5a);
        const float B0 = __shfl_sync(FULL, v4p0, s5b);
        const float B1 = __shfl_sync(FULL, v4p1, s5b);
        const float pa = hi ? A1 : A0;
        const float pb = hi ? B1 : B0;
        v5 = nck_eval(fmaf(w5a, pa, fmaf(w5b, pb, bb5)), cA, dA, cB, dB, cG);
    }
    // v5: lane = 8*e + k

    // ---- level 6: N=4 (lane = 4e + k, lanes 0-15 valid) ----
    float v6;
    {
        const int k6 = lane & 3;
        const int e6 = lane >> 2;
        const int s6 = (8 * e6 + 7 - 2 * k6) & 31;
        const float w6a = sm[L6W + 2 * k6], w6b = sm[L6W + 2 * k6 + 1];
        const float bb6 = sm[L6B + k6];
        const float pa = __shfl_sync(FULL, v5, s6);
        const float pb = __shfl_sync(FULL, v5, (s6 - 1) & 31);
        v6 = nck_eval(fmaf(w6a, pa, fmaf(w6b, pb, bb6)), cA, dA, cB, dB, cG);
    }

    // ---- level 7: N=2 (lane = 2e + k, lanes 0-7 valid) ----
    float v7;
    {
        const int k7 = lane & 1;
        const int e7 = (lane >> 1) & 7;
        const int s7 = (4 * e7 + 3 - 2 * k7) & 31;
        const float w7a = sm[L7W + 2 * k7], w7b = sm[L7W + 2 * k7 + 1];
        const float bb7 = sm[L7B + k7];
        const float pa = __shfl_sync(FULL, v6, s7);
        const float pb = __shfl_sync(FULL, v6, (s7 - 1) & 31);
        v7 = nck_eval(fmaf(w7a, pa, fmaf(w7b, pb, bb7)), cA, dA, cB, dB, cG);
    }

    // ---- level 8: N=1 (lane = e, lanes 0-3 valid) ----
    {
        const int e8 = lane & 3;
        const float pa = __shfl_sync(FULL, v7, (2 * e8 + 1) & 31);
        const float pb = __shfl_sync(FULL, v7, (2 * e8) & 31);
        const float v8 = nck_eval(fmaf(sm[L8W], pa, fmaf(sm[L8W + 1], pb, sm[L8B])),
                                  cA, dA, cB, dB, cG);
        if (lane < 4 && e0 + lane < B) {
            const float t = fmaf(v8, sm[SC + 3], sm[SC + 4]);
            out[e0 + lane] = rcpf(1.0f + ex2f(-t * L2E));
        }
    }
}

extern "C" void kernel_launch(void* const* d_in, const int* in_sizes, int n_in,
                              void* d_out, int out_size) {
    const float* x = (const float*)d_in[0];
    TreeParams P;
    if (in_sizes[2] == 511) {
        for (int l = 0; l < 9; ++l) {
            P.w[l] = (const float*)d_in[1 + 2 * l];
            P.b[l] = (const float*)d_in[2 + 2 * l];
        }
    } else {
        for (int l = 0; l < 9; ++l) {
            P.w[l] = (const float*)d_in[1 + l];
            P.b[l] = (const float*)d_in[10 + l];
        }
    }
    P.alpha  = (const float*)d_in[19];
    P.beta   = (const float*)d_in[20];
    P.gamma  = (const float*)d_in[21];
    P.root_w = (const float*)d_in[22];
    P.root_b = (const float*)d_in[23];

    const int B = in_sizes[0] / 256;              // 32768
    const int warps = (B + 3) / 4;                // 4 elements per warp
    const int grid = (warps + 7) / 8;             // 8 warps per 256-thread block
    asym_tree_kernel<<<grid, 256>>>(x, P, (float*)d_out, B);
}